// round 9
// baseline (speedup 1.0000x reference)
#include <cuda_runtime.h>
#include <cuda_bf16.h>
#include <cuda_fp8.h>
#include <cstdint>

#define BATCH 4096
#define DIM   256
#define NNEG  32768

// ---------------- scratch (device globals; no allocs allowed) ----------------
__device__ float g_rowsum[BATCH];
__device__ float g_colsum[BATCH];
__device__ float g_negsum[BATCH];
__device__ float g_diagdot[BATCH];      // exact fp32 q_i . p_i
__device__ int   g_off[BATCH];          // exclusive prefix of counts
__device__ uint32_t g_q8[BATCH * DIM / 4];   // e4m3x4 packed
__device__ uint32_t g_p8[BATCH * DIM / 4];

__device__ __forceinline__ uint32_t smem_u32(const void* p) {
    uint32_t a;
    asm("{ .reg .u64 t; cvta.to.shared.u64 t, %1; cvt.u32.u64 %0, t; }" : "=r"(a) : "l"(p));
    return a;
}

__device__ __forceinline__ float inv_tau(const float* log_tau) {
    float t = expf(log_tau[0]);
    t = fminf(fmaxf(t, 1e-4f), 1.0f);
    return 1.0f / t;
}

// ---------------- setup: fp32->fp8 convert + zero + exact diag + scan ----------------
// Blocks 0..255: 1024 threads; each converts one float4 of q and p, and the block
// reduces exact fp32 diag dots for its 16 rows. Block 256: offsets scan.
__global__ void convert_scan_kernel(const float* __restrict__ q, const float* __restrict__ p,
                                    const int* __restrict__ counts) {
    int tid = threadIdx.x;
    if (blockIdx.x < 256) {
        __shared__ float halves[32];
        int i = blockIdx.x * 1024 + tid;  // over BATCH*DIM/4 = 262144
        if (i < BATCH) { g_rowsum[i] = 0.f; g_colsum[i] = 0.f; g_negsum[i] = 0.f; }
        const float4 qa = ((const float4*)q)[i];
        const float4 pa = ((const float4*)p)[i];
        __nv_fp8x4_e4m3 q8(qa);
        __nv_fp8x4_e4m3 p8(pa);
        g_q8[i] = *reinterpret_cast<uint32_t*>(&q8);
        g_p8[i] = *reinterpret_cast<uint32_t*>(&p8);
        // exact diag: row = i>>6, 64 threads (2 warps) per row
        float part = qa.x * pa.x + qa.y * pa.y + qa.z * pa.z + qa.w * pa.w;
        #pragma unroll
        for (int m = 16; m >= 1; m >>= 1)
            part += __shfl_xor_sync(0xffffffffu, part, m);
        int w = tid >> 5;
        if ((tid & 31) == 0) halves[w] = part;
        __syncthreads();
        if ((tid & 63) == 0) {
            int row = blockIdx.x * 16 + (w >> 1);
            g_diagdot[row] = halves[w] + halves[w + 1];
        }
        return;
    }
    // ---- scan block: offsets only, fully parallel ----
    __shared__ int wsum[32];
    int lane = tid & 31, w = tid >> 5;
    int4 c4 = ((const int4*)counts)[tid];          // counts[4t .. 4t+3]
    int run = c4.x + c4.y + c4.z + c4.w;
    int incl = run;
    #pragma unroll
    for (int m = 1; m < 32; m <<= 1) {
        int t = __shfl_up_sync(0xffffffffu, incl, m);
        if (lane >= m) incl += t;
    }
    if (lane == 31) wsum[w] = incl;
    __syncthreads();
    if (tid < 32) {
        int v = wsum[tid];
        int s = v;
        #pragma unroll
        for (int m = 1; m < 32; m <<= 1) {
            int t = __shfl_up_sync(0xffffffffu, s, m);
            if (tid >= m) s += t;
        }
        wsum[tid] = s - v;   // exclusive warp base
    }
    __syncthreads();
    int excl = incl - run + wsum[w];
    int4 o;
    o.x = excl;
    o.y = o.x + c4.x;
    o.z = o.y + c4.y;
    o.w = o.z + c4.z;
    ((int4*)g_off)[tid] = o;
}

// ---------------- fused sim(FP8 MMA) + neg kernel ----------------
// Even blockIdx -> sim 128x128 tile (K=256 fp8 fully smem-resident, single buffer);
// odd blockIdx -> 32 negatives.
#define STRIDE     272                   // 256B data + 16B pad; conflict-free ldmatrix
#define TILE_BYTES (128 * STRIDE)        // 34816 per operand
#define SM_TOTAL   (2 * TILE_BYTES)      // 69632

__device__ void sim_block(uint32_t sb, int tileIdx, const float* __restrict__ log_tau) {
    const int tid  = threadIdx.x;
    const int wid  = tid >> 5;
    const int lane = tid & 31;
    const int row0 = (tileIdx >> 5) * 128;
    const int col0 = (tileIdx & 31) * 128;
    const int warpM = (wid >> 1) * 32;
    const int warpN = (wid & 1) * 64;

    // ---- single-shot load: A (q rows) and B (p rows), fp8, 256B per row ----
    {
        const char* qa = (const char*)g_q8 + (size_t)row0 * 256;
        const char* pa = (const char*)g_p8 + (size_t)col0 * 256;
        #pragma unroll
        for (int it = 0; it < 8; it++) {
            int idx = it * 256 + tid;         // 0..2047
            int r = idx >> 4, s = idx & 15;   // row, 16B segment
            uint32_t dst = sb + r * STRIDE + s * 16;
            asm volatile("cp.async.cg.shared.global [%0], [%1], 16;"
                         :: "r"(dst), "l"(qa + r * 256 + s * 16));
            asm volatile("cp.async.cg.shared.global [%0], [%1], 16;"
                         :: "r"(dst + TILE_BYTES), "l"(pa + r * 256 + s * 16));
        }
    }
    asm volatile("cp.async.commit_group;" ::: "memory");
    asm volatile("cp.async.wait_group 0;" ::: "memory");
    __syncthreads();

    // ---- MMA: 8 k-steps of k32 (fp8 e4m3), byte-addressing identical to bf16 path ----
    const uint32_t aAddr = sb + (uint32_t)(warpM + (lane & 15)) * STRIDE
                         + (uint32_t)(lane >> 4) * 16;
    const uint32_t bAddr = sb + TILE_BYTES
                         + (uint32_t)(warpN + (lane & 7) + ((lane >> 4) << 3)) * STRIDE
                         + (uint32_t)((lane >> 3) & 1) * 16;

    float acc[2][8][4];
    #pragma unroll
    for (int mi = 0; mi < 2; mi++)
        #pragma unroll
        for (int ni = 0; ni < 8; ni++)
            #pragma unroll
            for (int r = 0; r < 4; r++) acc[mi][ni][r] = 0.f;

    #pragma unroll
    for (int s = 0; s < 8; s++) {
        const uint32_t koff = (uint32_t)s * 32;
        uint32_t a[2][4];
        #pragma unroll
        for (int mi = 0; mi < 2; mi++) {
            asm volatile("ldmatrix.sync.aligned.m8n8.x4.shared.b16 {%0,%1,%2,%3}, [%4];"
                : "=r"(a[mi][0]), "=r"(a[mi][1]), "=r"(a[mi][2]), "=r"(a[mi][3])
                : "r"(aAddr + mi * (16 * STRIDE) + koff));
        }
        uint32_t b[4][4];
        #pragma unroll
        for (int nb = 0; nb < 4; nb++) {
            asm volatile("ldmatrix.sync.aligned.m8n8.x4.shared.b16 {%0,%1,%2,%3}, [%4];"
                : "=r"(b[nb][0]), "=r"(b[nb][1]), "=r"(b[nb][2]), "=r"(b[nb][3])
                : "r"(bAddr + nb * (16 * STRIDE) + koff));
        }
        #pragma unroll
        for (int mi = 0; mi < 2; mi++)
            #pragma unroll
            for (int nb = 0; nb < 4; nb++)
                #pragma unroll
                for (int sub = 0; sub < 2; sub++) {
                    float* d = acc[mi][nb * 2 + sub];
                    asm volatile(
                        "mma.sync.aligned.m16n8k32.row.col.f32.e4m3.e4m3.f32 "
                        "{%0,%1,%2,%3}, {%4,%5,%6,%7}, {%8,%9}, {%0,%1,%2,%3};"
                        : "+f"(d[0]), "+f"(d[1]), "+f"(d[2]), "+f"(d[3])
                        : "r"(a[mi][0]), "r"(a[mi][1]), "r"(a[mi][2]), "r"(a[mi][3]),
                          "r"(b[nb][sub * 2]), "r"(b[nb][sub * 2 + 1]));
                }
    }

    // ---- epilogue: scale, exp, row/col sums (diag handled exactly elsewhere) ----
    const float scale = inv_tau(log_tau);
    const int g   = lane >> 2;

    float rsum[4];
    #pragma unroll
    for (int k = 0; k < 4; k++) rsum[k] = 0.f;
    float csum[8][2];
    #pragma unroll
    for (int ni = 0; ni < 8; ni++) { csum[ni][0] = 0.f; csum[ni][1] = 0.f; }

    #pragma unroll
    for (int mi = 0; mi < 2; mi++)
        #pragma unroll
        for (int ni = 0; ni < 8; ni++)
            #pragma unroll
            for (int r = 0; r < 4; r++) {
                int h = r >> 1, c = r & 1;
                float e = __expf(acc[mi][ni][r] * scale);
                rsum[mi * 2 + h] += e;
                csum[ni][c] += e;
            }

    #pragma unroll
    for (int k = 0; k < 4; k++) {
        rsum[k] += __shfl_xor_sync(0xffffffffu, rsum[k], 1);
        rsum[k] += __shfl_xor_sync(0xffffffffu, rsum[k], 2);
    }
    if ((lane & 3) == 0) {
        #pragma unroll
        for (int k = 0; k < 4; k++) {
            int lr = warpM + (k >> 1) * 16 + (k & 1) * 8 + g;
            atomicAdd(&g_rowsum[row0 + lr], rsum[k]);
        }
    }
    #pragma unroll
    for (int ni = 0; ni < 8; ni++)
        #pragma unroll
        for (int c = 0; c < 2; c++) {
            csum[ni][c] += __shfl_xor_sync(0xffffffffu, csum[ni][c], 4);
            csum[ni][c] += __shfl_xor_sync(0xffffffffu, csum[ni][c], 8);
            csum[ni][c] += __shfl_xor_sync(0xffffffffu, csum[ni][c], 16);
        }
    if (lane < 4) {
        #pragma unroll
        for (int ni = 0; ni < 8; ni++)
            #pragma unroll
            for (int c = 0; c < 2; c++) {
                int lc = warpN + ni * 8 + lane * 2 + c;
                atomicAdd(&g_colsum[col0 + lc], csum[ni][c]);
            }
    }
}

// neg block: 32 negatives, 8 threads each (fp32 exact); qid via binary search.
__device__ void neg_block(int negBlk, const float* __restrict__ q,
                          const float* __restrict__ nem,
                          const float* __restrict__ log_tau) {
    const int tid = threadIdx.x;
    const int neg = negBlk * 32 + (tid >> 3);
    const int l8  = tid & 7;

    int lo = 0, hi = BATCH - 1;
    #pragma unroll
    for (int it = 0; it < 12; it++) {
        int mid = (lo + hi + 1) >> 1;
        if (__ldg(&g_off[mid]) <= neg) lo = mid; else hi = mid - 1;
    }
    const int qid = lo;

    const float4* nr = (const float4*)(nem + (size_t)neg * DIM);
    const float4* qr = (const float4*)(q   + (size_t)qid * DIM);

    float4 nv[8], qv[8];
    #pragma unroll
    for (int j = 0; j < 8; j++) nv[j] = nr[l8 + j * 8];
    #pragma unroll
    for (int j = 0; j < 8; j++) qv[j] = qr[l8 + j * 8];

    float dot = 0.f;
    #pragma unroll
    for (int j = 0; j < 8; j++)
        dot += qv[j].x * nv[j].x + qv[j].y * nv[j].y
             + qv[j].z * nv[j].z + qv[j].w * nv[j].w;
    dot += __shfl_xor_sync(0xffffffffu, dot, 1);
    dot += __shfl_xor_sync(0xffffffffu, dot, 2);
    dot += __shfl_xor_sync(0xffffffffu, dot, 4);
    if (l8 == 0)
        atomicAdd(&g_negsum[qid], __expf(dot * inv_tau(log_tau)));
}

__global__ __launch_bounds__(256, 2)
void fused_kernel(const float* __restrict__ q, const float* __restrict__ nem,
                  const float* __restrict__ log_tau)
{
    extern __shared__ char smem[];
    const int bid = blockIdx.x;
    if (bid & 1) {
        neg_block(bid >> 1, q, nem, log_tau);
    } else {
        sim_block(smem_u32(smem), bid >> 1, log_tau);
    }
}

// ---------------- finalize ----------------
__global__ void finalize_kernel(const float* __restrict__ log_tau, float* __restrict__ out) {
    __shared__ float sh[256];
    int tid = threadIdx.x;
    float scale = inv_tau(log_tau);
    float s = 0.f;
    for (int i = tid; i < BATCH; i += 256) {
        float d  = g_diagdot[i] * scale;
        float lq = logf(g_rowsum[i] + g_negsum[i]) - d;
        float lp = logf(g_colsum[i]) - d;
        s += 0.5f * (lq + lp);
    }
    sh[tid] = s;
    __syncthreads();
    #pragma unroll
    for (int off = 128; off >= 32; off >>= 1) {
        if (tid < off) sh[tid] += sh[tid + off];
        __syncthreads();
    }
    if (tid < 32) {
        float v = sh[tid];
        #pragma unroll
        for (int m = 16; m >= 1; m >>= 1)
            v += __shfl_xor_sync(0xffffffffu, v, m);
        if (tid == 0) out[0] = v / (float)BATCH;
    }
}

extern "C" void kernel_launch(void* const* d_in, const int* in_sizes, int n_in,
                              void* d_out, int out_size) {
    const float* q   = (const float*)d_in[0];
    const float* p   = (const float*)d_in[1];
    const float* nem = (const float*)d_in[2];
    const int*   cnt = (const int*)  d_in[3];
    const float* lt  = (const float*)d_in[4];
    float* out = (float*)d_out;

    cudaFuncSetAttribute(fused_kernel,
                         cudaFuncAttributeMaxDynamicSharedMemorySize, SM_TOTAL);

    convert_scan_kernel<<<257, 1024>>>(q, p, cnt);
    fused_kernel<<<2048, 256, SM_TOTAL>>>(q, nem, lt);
    finalize_kernel<<<1, 256>>>(lt, out);
}

// round 10
// speedup vs baseline: 1.0933x; 1.0933x over previous
#include <cuda_runtime.h>
#include <cuda_bf16.h>
#include <cuda_fp8.h>
#include <cstdint>

#define BATCH 4096
#define DIM   256
#define NNEG  32768

// ---------------- scratch (device globals; no allocs allowed) ----------------
__device__ float g_rowsum[BATCH];
__device__ float g_colsum[BATCH];
__device__ float g_negsum[BATCH];
__device__ float g_diagdot[BATCH];      // exact fp32 q_i . p_i
__device__ int   g_off[BATCH];          // exclusive prefix of counts
__device__ uint32_t g_q8[BATCH * DIM / 4];   // e4m3x4 packed
__device__ uint32_t g_p8[BATCH * DIM / 4];

__device__ __forceinline__ uint32_t smem_u32(const void* p) {
    uint32_t a;
    asm("{ .reg .u64 t; cvta.to.shared.u64 t, %1; cvt.u32.u64 %0, t; }" : "=r"(a) : "l"(p));
    return a;
}

__device__ __forceinline__ float inv_tau(const float* log_tau) {
    float t = expf(log_tau[0]);
    t = fminf(fmaxf(t, 1e-4f), 1.0f);
    return 1.0f / t;
}

// ---------------- setup: fp32->fp8 convert + zero + exact diag + scan ----------------
__global__ void convert_scan_kernel(const float* __restrict__ q, const float* __restrict__ p,
                                    const int* __restrict__ counts) {
    int tid = threadIdx.x;
    if (blockIdx.x < 256) {
        __shared__ float halves[32];
        int i = blockIdx.x * 1024 + tid;  // over BATCH*DIM/4 = 262144
        if (i < BATCH) { g_rowsum[i] = 0.f; g_colsum[i] = 0.f; g_negsum[i] = 0.f; }
        const float4 qa = ((const float4*)q)[i];
        const float4 pa = ((const float4*)p)[i];
        __nv_fp8x4_e4m3 q8(qa);
        __nv_fp8x4_e4m3 p8(pa);
        g_q8[i] = *reinterpret_cast<uint32_t*>(&q8);
        g_p8[i] = *reinterpret_cast<uint32_t*>(&p8);
        // exact diag: 64 threads (2 warps) per row
        float part = qa.x * pa.x + qa.y * pa.y + qa.z * pa.z + qa.w * pa.w;
        #pragma unroll
        for (int m = 16; m >= 1; m >>= 1)
            part += __shfl_xor_sync(0xffffffffu, part, m);
        int w = tid >> 5;
        if ((tid & 31) == 0) halves[w] = part;
        __syncthreads();
        if ((tid & 63) == 0) {
            int row = blockIdx.x * 16 + (w >> 1);
            g_diagdot[row] = halves[w] + halves[w + 1];
        }
        return;
    }
    // ---- scan block: offsets only, fully parallel ----
    __shared__ int wsum[32];
    int lane = tid & 31, w = tid >> 5;
    int4 c4 = ((const int4*)counts)[tid];
    int run = c4.x + c4.y + c4.z + c4.w;
    int incl = run;
    #pragma unroll
    for (int m = 1; m < 32; m <<= 1) {
        int t = __shfl_up_sync(0xffffffffu, incl, m);
        if (lane >= m) incl += t;
    }
    if (lane == 31) wsum[w] = incl;
    __syncthreads();
    if (tid < 32) {
        int v = wsum[tid];
        int s = v;
        #pragma unroll
        for (int m = 1; m < 32; m <<= 1) {
            int t = __shfl_up_sync(0xffffffffu, s, m);
            if (tid >= m) s += t;
        }
        wsum[tid] = s - v;
    }
    __syncthreads();
    int excl = incl - run + wsum[w];
    int4 o;
    o.x = excl;
    o.y = o.x + c4.x;
    o.z = o.y + c4.y;
    o.w = o.z + c4.z;
    ((int4*)g_off)[tid] = o;
}

// ---------------- fused kernel: each block = one 128x128 sim tile + 32 negatives ----------------
#define STRIDE     272                   // 256B data + 16B pad; conflict-free ldmatrix
#define TILE_BYTES (128 * STRIDE)        // 34816 per operand
#define SM_TOTAL   (2 * TILE_BYTES)      // 69632

__global__ __launch_bounds__(256, 2)
void fused_kernel(const float* __restrict__ q, const float* __restrict__ nem,
                  const float* __restrict__ log_tau)
{
    extern __shared__ char smem[];
    const uint32_t sb = smem_u32(smem);
    const int tid  = threadIdx.x;
    const int wid  = tid >> 5;
    const int lane = tid & 31;
    const int bid  = blockIdx.x;           // 0..1023
    const int row0 = (bid >> 5) * 128;
    const int col0 = (bid & 31) * 128;
    const int warpM = (wid >> 1) * 32;
    const int warpN = (wid & 1) * 64;

    // ---- kick off tile loads (fp8, 256B per row, single shot) ----
    {
        const char* qa = (const char*)g_q8 + (size_t)row0 * 256;
        const char* pa = (const char*)g_p8 + (size_t)col0 * 256;
        #pragma unroll
        for (int it = 0; it < 8; it++) {
            int idx = it * 256 + tid;         // 0..2047
            int r = idx >> 4, s = idx & 15;
            uint32_t dst = sb + r * STRIDE + s * 16;
            asm volatile("cp.async.cg.shared.global [%0], [%1], 16;"
                         :: "r"(dst), "l"(qa + r * 256 + s * 16));
            asm volatile("cp.async.cg.shared.global [%0], [%1], 16;"
                         :: "r"(dst + TILE_BYTES), "l"(pa + r * 256 + s * 16));
        }
    }
    asm volatile("cp.async.commit_group;" ::: "memory");

    // ---- overlap: binary-search the qid for this thread's negative ----
    // (dependent L2 chain runs while cp.async data is in flight)
    const int neg = bid * 32 + (tid >> 3);  // 8 threads per negative
    const int l8  = tid & 7;
    int qid;
    {
        int lo = 0, hi = BATCH - 1;
        #pragma unroll
        for (int it = 0; it < 12; it++) {
            int mid = (lo + hi + 1) >> 1;
            if (__ldg(&g_off[mid]) <= neg) lo = mid; else hi = mid - 1;
        }
        qid = lo;
    }
    const float scale = inv_tau(log_tau);

    asm volatile("cp.async.wait_group 0;" ::: "memory");
    __syncthreads();

    // ---- MMA: 8 k-steps of k32 (fp8 e4m3) ----
    const uint32_t aAddr = sb + (uint32_t)(warpM + (lane & 15)) * STRIDE
                         + (uint32_t)(lane >> 4) * 16;
    const uint32_t bAddr = sb + TILE_BYTES
                         + (uint32_t)(warpN + (lane & 7) + ((lane >> 4) << 3)) * STRIDE
                         + (uint32_t)((lane >> 3) & 1) * 16;

    float acc[2][8][4];
    #pragma unroll
    for (int mi = 0; mi < 2; mi++)
        #pragma unroll
        for (int ni = 0; ni < 8; ni++)
            #pragma unroll
            for (int r = 0; r < 4; r++) acc[mi][ni][r] = 0.f;

    #pragma unroll
    for (int s = 0; s < 8; s++) {
        const uint32_t koff = (uint32_t)s * 32;
        uint32_t a[2][4];
        #pragma unroll
        for (int mi = 0; mi < 2; mi++) {
            asm volatile("ldmatrix.sync.aligned.m8n8.x4.shared.b16 {%0,%1,%2,%3}, [%4];"
                : "=r"(a[mi][0]), "=r"(a[mi][1]), "=r"(a[mi][2]), "=r"(a[mi][3])
                : "r"(aAddr + mi * (16 * STRIDE) + koff));
        }
        uint32_t b[4][4];
        #pragma unroll
        for (int nb = 0; nb < 4; nb++) {
            asm volatile("ldmatrix.sync.aligned.m8n8.x4.shared.b16 {%0,%1,%2,%3}, [%4];"
                : "=r"(b[nb][0]), "=r"(b[nb][1]), "=r"(b[nb][2]), "=r"(b[nb][3])
                : "r"(bAddr + nb * (16 * STRIDE) + koff));
        }
        #pragma unroll
        for (int mi = 0; mi < 2; mi++)
            #pragma unroll
            for (int nb = 0; nb < 4; nb++)
                #pragma unroll
                for (int sub = 0; sub < 2; sub++) {
                    float* d = acc[mi][nb * 2 + sub];
                    asm volatile(
                        "mma.sync.aligned.m16n8k32.row.col.f32.e4m3.e4m3.f32 "
                        "{%0,%1,%2,%3}, {%4,%5,%6,%7}, {%8,%9}, {%0,%1,%2,%3};"
                        : "+f"(d[0]), "+f"(d[1]), "+f"(d[2]), "+f"(d[3])
                        : "r"(a[mi][0]), "r"(a[mi][1]), "r"(a[mi][2]), "r"(a[mi][3]),
                          "r"(b[nb][sub * 2]), "r"(b[nb][sub * 2 + 1]));
                }
    }

    // ---- epilogue: exp, row/col sums (diag handled exactly in finalize) ----
    const int g = lane >> 2;

    float rsum[4];
    #pragma unroll
    for (int k = 0; k < 4; k++) rsum[k] = 0.f;
    float csum[8][2];
    #pragma unroll
    for (int ni = 0; ni < 8; ni++) { csum[ni][0] = 0.f; csum[ni][1] = 0.f; }

    #pragma unroll
    for (int mi = 0; mi < 2; mi++)
        #pragma unroll
        for (int ni = 0; ni < 8; ni++)
            #pragma unroll
            for (int r = 0; r < 4; r++) {
                int h = r >> 1, c = r & 1;
                float e = __expf(acc[mi][ni][r] * scale);
                rsum[mi * 2 + h] += e;
                csum[ni][c] += e;
            }

    #pragma unroll
    for (int k = 0; k < 4; k++) {
        rsum[k] += __shfl_xor_sync(0xffffffffu, rsum[k], 1);
        rsum[k] += __shfl_xor_sync(0xffffffffu, rsum[k], 2);
    }
    if ((lane & 3) == 0) {
        #pragma unroll
        for (int k = 0; k < 4; k++) {
            int lr = warpM + (k >> 1) * 16 + (k & 1) * 8 + g;
            atomicAdd(&g_rowsum[row0 + lr], rsum[k]);
        }
    }
    #pragma unroll
    for (int ni = 0; ni < 8; ni++)
        #pragma unroll
        for (int c = 0; c < 2; c++) {
            csum[ni][c] += __shfl_xor_sync(0xffffffffu, csum[ni][c], 4);
            csum[ni][c] += __shfl_xor_sync(0xffffffffu, csum[ni][c], 8);
            csum[ni][c] += __shfl_xor_sync(0xffffffffu, csum[ni][c], 16);
        }
    if (lane < 4) {
        #pragma unroll
        for (int ni = 0; ni < 8; ni++)
            #pragma unroll
            for (int c = 0; c < 2; c++) {
                int lc = warpN + ni * 8 + lane * 2 + c;
                atomicAdd(&g_colsum[col0 + lc], csum[ni][c]);
            }
    }

    // ---- negatives tail: 32 negs, 8 threads each (fp32 exact, L2-hot) ----
    {
        const float4* nr = (const float4*)(nem + (size_t)neg * DIM);
        const float4* qr = (const float4*)(q   + (size_t)qid * DIM);
        float4 nv[8], qv[8];
        #pragma unroll
        for (int j = 0; j < 8; j++) nv[j] = nr[l8 + j * 8];
        #pragma unroll
        for (int j = 0; j < 8; j++) qv[j] = qr[l8 + j * 8];
        float dot = 0.f;
        #pragma unroll
        for (int j = 0; j < 8; j++)
            dot += qv[j].x * nv[j].x + qv[j].y * nv[j].y
                 + qv[j].z * nv[j].z + qv[j].w * nv[j].w;
        dot += __shfl_xor_sync(0xffffffffu, dot, 1);
        dot += __shfl_xor_sync(0xffffffffu, dot, 2);
        dot += __shfl_xor_sync(0xffffffffu, dot, 4);
        if (l8 == 0)
            atomicAdd(&g_negsum[qid], __expf(dot * scale));
    }
}

// ---------------- finalize ----------------
__global__ void finalize_kernel(const float* __restrict__ log_tau, float* __restrict__ out) {
    __shared__ float sh[256];
    int tid = threadIdx.x;
    float scale = inv_tau(log_tau);
    float s = 0.f;
    for (int i = tid; i < BATCH; i += 256) {
        float d  = g_diagdot[i] * scale;
        float lq = logf(g_rowsum[i] + g_negsum[i]) - d;
        float lp = logf(g_colsum[i]) - d;
        s += 0.5f * (lq + lp);
    }
    sh[tid] = s;
    __syncthreads();
    #pragma unroll
    for (int off = 128; off >= 32; off >>= 1) {
        if (tid < off) sh[tid] += sh[tid + off];
        __syncthreads();
    }
    if (tid < 32) {
        float v = sh[tid];
        #pragma unroll
        for (int m = 16; m >= 1; m >>= 1)
            v += __shfl_xor_sync(0xffffffffu, v, m);
        if (tid == 0) out[0] = v / (float)BATCH;
    }
}

extern "C" void kernel_launch(void* const* d_in, const int* in_sizes, int n_in,
                              void* d_out, int out_size) {
    const float* q   = (const float*)d_in[0];
    const float* p   = (const float*)d_in[1];
    const float* nem = (const float*)d_in[2];
    const int*   cnt = (const int*)  d_in[3];
    const float* lt  = (const float*)d_in[4];
    float* out = (float*)d_out;

    cudaFuncSetAttribute(fused_kernel,
                         cudaFuncAttributeMaxDynamicSharedMemorySize, SM_TOTAL);

    convert_scan_kernel<<<257, 1024>>>(q, p, cnt);
    fused_kernel<<<1024, 256, SM_TOTAL>>>(q, nem, lt);
    finalize_kernel<<<1, 256>>>(lt, out);
}